// round 14
// baseline (speedup 1.0000x reference)
#include <cuda_runtime.h>
#include <cuda_fp16.h>
#include <cstdint>

#define N_NODES 50000
#define N_EDGES 800000
#define D 128
#define BN_EPS 1e-5f
#define SCAN_CHUNK 512
#define N_CHUNKS ((N_NODES + SCAN_CHUNK - 1) / SCAN_CHUNK)   // 98
#define SA 136                      // half stride for A/WT tiles (272B rows)
#define TILE_BYTES (128 * SA * 2)   // 34816
#define SM_AHI 0
#define SM_ALO TILE_BYTES           // 34816
#define SM_WT  (2 * TILE_BYTES)     // 69632
#define SM_MLP_TOTAL (3 * TILE_BYTES)         // 104448
#define SM_SC  SM_MLP_TOTAL
#define SM_PROJ_TOTAL (SM_MLP_TOTAL + 1024)

// Persistent scratch.
__device__ __align__(16) float g_z[N_NODES * D];     // fp32 node features
__device__ __align__(16) __half g_zh[N_NODES * D];   // fp16 mirror (agg gather)
__device__ __align__(16) float g_agg[N_NODES * D];   // aggregation (fp32)
__device__ float g_stats[2 * D];
__device__ int g_idx64;
__device__ int g_deg[N_NODES];
__device__ int g_cur[N_NODES];
__device__ int g_rowptr[N_NODES + 1];
__device__ int g_part[N_CHUNKS];
__device__ __align__(16) int2 g_epk[N_EDGES];        // packed (src, weight bits)

// ===========================================================================
// Prep: zero counters/stats, probe edge dtype, convert x -> fp16 mirror.
// ===========================================================================
__global__ void prep_kernel(const float* __restrict__ x,
                            const int* __restrict__ ei32) {
    int i = blockIdx.x * blockDim.x + threadIdx.x;   // 0 .. 1.6M
    if (i < N_NODES * D / 4) {
        float4 v = ((const float4*)x)[i];
        __half2 h0 = __floats2half2_rn(v.x, v.y);
        __half2 h1 = __floats2half2_rn(v.z, v.w);
        uint2 p;
        p.x = *(uint32_t*)&h0;
        p.y = *(uint32_t*)&h1;
        ((uint2*)g_zh)[i] = p;
    }
    if (i < N_NODES) g_deg[i] = 0;
    if (i < 2 * D) g_stats[i] = 0.f;
    if (i == 0) {
        int all_zero = 1;
#pragma unroll
        for (int k = 0; k < 64; k++)
            if (__ldg(&ei32[2 * k + 1]) != 0) all_zero = 0;
        g_idx64 = all_zero;
    }
}

__device__ __forceinline__ int load_src(const int* ei32, int e) {
    int s = g_idx64 ? __ldg(&ei32[2 * e]) : __ldg(&ei32[e]);
    return min(max(s, 0), N_NODES - 1);
}
__device__ __forceinline__ int load_dst(const int* ei32, int e) {
    int d = g_idx64 ? __ldg(&ei32[2 * N_EDGES + 2 * e]) : __ldg(&ei32[N_EDGES + e]);
    return min(max(d, 0), N_NODES - 1);
}

__global__ void hist_kernel(const int* __restrict__ ei32) {
    int e = blockIdx.x * blockDim.x + threadIdx.x;
    if (e >= N_EDGES) return;
    atomicAdd(&g_deg[load_dst(ei32, e)], 1);
}

// Phase 1: per-chunk exclusive scan + chunk totals in g_part.
__global__ void scan_partial_kernel() {
    __shared__ int wsum[16];
    int tid = threadIdx.x, lane = tid & 31, wid = tid >> 5;
    int i = blockIdx.x * SCAN_CHUNK + tid;
    int v = (i < N_NODES) ? g_deg[i] : 0;
    int x = v;
#pragma unroll
    for (int o = 1; o < 32; o <<= 1) {
        int y = __shfl_up_sync(0xFFFFFFFFu, x, o);
        if (lane >= o) x += y;
    }
    if (lane == 31) wsum[wid] = x;
    __syncthreads();
    if (wid == 0 && lane < 16) {
        int w = wsum[lane];
#pragma unroll
        for (int o = 1; o < 16; o <<= 1) {
            int y = __shfl_up_sync(0x0000FFFFu, w, o);
            if (lane >= o) w += y;
        }
        wsum[lane] = w;
    }
    __syncthreads();
    int base = (wid > 0) ? wsum[wid - 1] : 0;
    if (i < N_NODES) g_rowptr[i] = base + x - v;
    if (tid == SCAN_CHUNK - 1) g_part[blockIdx.x] = base + x;
}

// Phase 2 (fused): each 256-block spans exactly half of one 512-chunk; thread 0
// sums g_part[0..chunk) inline (<=97 adds). Last element also writes total.
__global__ void scan_add_kernel() {
    __shared__ int s_off;
    int i = blockIdx.x * blockDim.x + threadIdx.x;
    int chunk = (blockIdx.x * 256) >> 9;            // uniform within block
    if (threadIdx.x == 0) {
        int off = 0;
        for (int c = 0; c < chunk; c++) off += g_part[c];
        s_off = off;
    }
    __syncthreads();
    if (i < N_NODES) {
        int r = g_rowptr[i] + s_off;
        g_rowptr[i] = r;
        g_cur[i] = r;
    }
    if (i == N_NODES - 1) {
        int tot = s_off;
        for (int c = chunk; c < N_CHUNKS; c++) tot += g_part[c];
        g_rowptr[N_NODES] = tot;
    }
}

__global__ void scatter_kernel(const float* __restrict__ ew,
                               const int* __restrict__ ei32) {
    int e = blockIdx.x * blockDim.x + threadIdx.x;
    if (e >= N_EDGES) return;
    int src = load_src(ei32, e);
    int dst = load_dst(ei32, e);
    int pos = atomicAdd(&g_cur[dst], 1);
    g_epk[pos] = make_int2(src, __float_as_int(__ldg(&ew[e])));
}

// ===========================================================================
// CSR aggregation: fp16 gather (256B rows, half the L2 traffic), fp32 accum.
// One warp per node; lane covers 4 columns via one 8B load per edge.
// ===========================================================================
__global__ void agg_kernel() {
    int node = (blockIdx.x * blockDim.x + threadIdx.x) >> 5;
    if (node >= N_NODES) return;
    int lane = threadIdx.x & 31;

    int beg = __ldg(&g_rowptr[node]);
    int end = __ldg(&g_rowptr[node + 1]);
    float4 acc = make_float4(0.f, 0.f, 0.f, 0.f);
    int e = beg;
#define AGG_ONE(EE)                                                        \
    do {                                                                   \
        int2 pk = __ldg(&g_epk[EE]);                                       \
        float w = __int_as_float(pk.y);                                    \
        uint2 v = __ldg(&((const uint2*)(g_zh + (size_t)pk.x * D))[lane]); \
        float2 f0 = __half22float2(*(__half2*)&v.x);                       \
        float2 f1 = __half22float2(*(__half2*)&v.y);                       \
        acc.x = fmaf(f0.x, w, acc.x); acc.y = fmaf(f0.y, w, acc.y);        \
        acc.z = fmaf(f1.x, w, acc.z); acc.w = fmaf(f1.y, w, acc.w);        \
    } while (0)
    for (; e + 4 <= end; e += 4) {
        AGG_ONE(e); AGG_ONE(e + 1); AGG_ONE(e + 2); AGG_ONE(e + 3);
    }
    for (; e < end; e++) AGG_ONE(e);
#undef AGG_ONE
    ((float4*)(g_agg + (size_t)node * D))[lane] = acc;
}

// ===========================================================================
// HMMA GEMM machinery (mma.sync m16n8k16, fp16 in / fp32 accum) — round 13.
// ===========================================================================
__device__ __forceinline__ void mma16816(float* c, uint32_t a0, uint32_t a1,
                                         uint32_t a2, uint32_t a3,
                                         uint32_t b0, uint32_t b1) {
    asm volatile(
        "mma.sync.aligned.m16n8k16.row.col.f32.f16.f16.f32 "
        "{%0,%1,%2,%3}, {%4,%5,%6,%7}, {%8,%9}, {%0,%1,%2,%3};"
        : "+f"(c[0]), "+f"(c[1]), "+f"(c[2]), "+f"(c[3])
        : "r"(a0), "r"(a1), "r"(a2), "r"(a3), "r"(b0), "r"(b1));
}

template <bool DUAL>
__device__ __forceinline__ void gemm_pass(const __half* sAhi, const __half* sAlo,
                                          const __half* sWT, float C[16][4],
                                          int wid, int g, int ti) {
    for (int ks = 0; ks < 8; ks++) {
        int k0 = ks * 16;
        int ra = (wid * 16 + g) * SA + ti * 2 + k0;
        uint32_t h0 = *(const uint32_t*)&sAhi[ra];
        uint32_t h1 = *(const uint32_t*)&sAhi[ra + 8 * SA];
        uint32_t h2 = *(const uint32_t*)&sAhi[ra + 8];
        uint32_t h3 = *(const uint32_t*)&sAhi[ra + 8 * SA + 8];
        uint32_t l0 = 0, l1 = 0, l2 = 0, l3 = 0;
        if (DUAL) {
            l0 = *(const uint32_t*)&sAlo[ra];
            l1 = *(const uint32_t*)&sAlo[ra + 8 * SA];
            l2 = *(const uint32_t*)&sAlo[ra + 8];
            l3 = *(const uint32_t*)&sAlo[ra + 8 * SA + 8];
        }
#pragma unroll
        for (int nt = 0; nt < 16; nt++) {
            int rb = (nt * 8 + g) * SA + ti * 2 + k0;
            uint32_t b0 = *(const uint32_t*)&sWT[rb];
            uint32_t b1 = *(const uint32_t*)&sWT[rb + 8];
            mma16816(C[nt], h0, h1, h2, h3, b0, b1);
            if (DUAL) mma16816(C[nt], l0, l1, l2, l3, b0, b1);
        }
    }
}

__device__ __forceinline__ void fill_wt(const float* __restrict__ W, __half* sWT,
                                        int tid, int part) {
    for (int idx = tid; idx < D * D; idx += 256) {
        int k = idx >> 7, n = idx & 127;
        float w = __ldg(&W[idx]);
        __half hi = __float2half_rn(w);
        sWT[n * SA + k] = part ? __float2half_rn(w - __half2float(hi)) : hi;
    }
}

__device__ __forceinline__ uint32_t pack_halves(float a, float b) {
    __half ha = __float2half_rn(a), hb = __float2half_rn(b);
    return (uint32_t)__half_as_ushort(ha) | ((uint32_t)__half_as_ushort(hb) << 16);
}

// ===========================================================================
// Fused GIN layer on HMMA; epilogue 2 also writes the fp16 mirror (layers 0,1)
// and fused BN statistics (layer 2).
// ===========================================================================
__global__ void __launch_bounds__(256)
mlp_mma_kernel(const float* __restrict__ xin,
               const float* __restrict__ W1s,
               const float* __restrict__ b1s,
               const float* __restrict__ W2s,
               const float* __restrict__ b2s,
               const float* __restrict__ epsp,
               int layer) {
    extern __shared__ char smc[];
    __half* sAhi = (__half*)(smc + SM_AHI);
    __half* sAlo = (__half*)(smc + SM_ALO);
    __half* sWT  = (__half*)(smc + SM_WT);

    int tid = threadIdx.x;
    int wid = tid >> 5, lane = tid & 31;
    int g = lane >> 2, ti = lane & 3;
    int row0 = blockIdx.x * 128;

    const float* zin = (layer == 0) ? xin : g_z;
    const float* W1 = W1s + layer * D * D;
    const float* W2 = W2s + layer * D * D;
    const float* b1 = b1s + layer * D;
    const float* b2 = b2s + layer * D;
    const float onePlusEps = 1.f + __ldg(&epsp[layer]);

    for (int idx = tid; idx < D * D; idx += 256) {
        int r = idx >> 7, k = idx & 127;
        int gr = row0 + r;
        float hv = 0.f;
        if (gr < N_NODES)
            hv = fmaf(onePlusEps, zin[(size_t)gr * D + k], g_agg[(size_t)gr * D + k]);
        __half hi = __float2half_rn(hv);
        sAhi[r * SA + k] = hi;
        sAlo[r * SA + k] = __float2half_rn(hv - __half2float(hi));
    }
    fill_wt(W1, sWT, tid, 0);
    __syncthreads();

    float C[16][4];
#pragma unroll
    for (int nt = 0; nt < 16; nt++)
#pragma unroll
        for (int j = 0; j < 4; j++) C[nt][j] = 0.f;

    gemm_pass<true>(sAhi, sAlo, sWT, C, wid, g, ti);
    __syncthreads();
    fill_wt(W1, sWT, tid, 1);
    __syncthreads();
    gemm_pass<false>(sAhi, sAlo, sWT, C, wid, g, ti);
    __syncthreads();

    // Epilogue 1: T = relu(C + b1) -> A tiles; zero C
    {
        int r0 = wid * 16 + g;
#pragma unroll
        for (int nt = 0; nt < 16; nt++) {
            int c0 = nt * 8 + ti * 2;
            float bv0 = __ldg(&b1[c0]), bv1 = __ldg(&b1[c0 + 1]);
            float t00 = fmaxf(C[nt][0] + bv0, 0.f);
            float t01 = fmaxf(C[nt][1] + bv1, 0.f);
            float t10 = fmaxf(C[nt][2] + bv0, 0.f);
            float t11 = fmaxf(C[nt][3] + bv1, 0.f);
            uint32_t p0 = pack_halves(t00, t01);
            uint32_t p1 = pack_halves(t10, t11);
            *(uint32_t*)&sAhi[r0 * SA + c0] = p0;
            *(uint32_t*)&sAhi[(r0 + 8) * SA + c0] = p1;
            __half h00 = __ushort_as_half((unsigned short)(p0 & 0xFFFF));
            __half h01 = __ushort_as_half((unsigned short)(p0 >> 16));
            __half h10 = __ushort_as_half((unsigned short)(p1 & 0xFFFF));
            __half h11 = __ushort_as_half((unsigned short)(p1 >> 16));
            *(uint32_t*)&sAlo[r0 * SA + c0] =
                pack_halves(t00 - __half2float(h00), t01 - __half2float(h01));
            *(uint32_t*)&sAlo[(r0 + 8) * SA + c0] =
                pack_halves(t10 - __half2float(h10), t11 - __half2float(h11));
#pragma unroll
            for (int j = 0; j < 4; j++) C[nt][j] = 0.f;
        }
    }
    fill_wt(W2, sWT, tid, 0);
    __syncthreads();

    gemm_pass<true>(sAhi, sAlo, sWT, C, wid, g, ti);
    __syncthreads();
    fill_wt(W2, sWT, tid, 1);
    __syncthreads();
    gemm_pass<false>(sAhi, sAlo, sWT, C, wid, g, ti);

    // Epilogue 2: z = relu(C + b2) -> g_z (+ fp16 mirror); BN stats on layer 2
    float* sPartS = (float*)(smc + SM_ALO);
    float* sPartQ = sPartS + 1024;
    {
        int lr = wid * 16 + g;
        int gr0 = row0 + lr, gr1 = gr0 + 8;
#pragma unroll
        for (int nt = 0; nt < 16; nt++) {
            int c0 = nt * 8 + ti * 2;
            float bv0 = __ldg(&b2[c0]), bv1 = __ldg(&b2[c0 + 1]);
            float v00 = fmaxf(C[nt][0] + bv0, 0.f);
            float v01 = fmaxf(C[nt][1] + bv1, 0.f);
            float v10 = fmaxf(C[nt][2] + bv0, 0.f);
            float v11 = fmaxf(C[nt][3] + bv1, 0.f);
            if (gr0 < N_NODES) {
                *(float2*)&g_z[(size_t)gr0 * D + c0] = make_float2(v00, v01);
                if (layer < 2)
                    *(uint32_t*)&g_zh[(size_t)gr0 * D + c0] = pack_halves(v00, v01);
            } else { v00 = v01 = 0.f; }
            if (gr1 < N_NODES) {
                *(float2*)&g_z[(size_t)gr1 * D + c0] = make_float2(v10, v11);
                if (layer < 2)
                    *(uint32_t*)&g_zh[(size_t)gr1 * D + c0] = pack_halves(v10, v11);
            } else { v10 = v11 = 0.f; }
            if (layer == 2) {
                float s0 = v00 + v10, s1 = v01 + v11;
                float q0 = v00 * v00 + v10 * v10, q1 = v01 * v01 + v11 * v11;
#pragma unroll
                for (int o = 4; o < 32; o <<= 1) {
                    s0 += __shfl_xor_sync(0xFFFFFFFFu, s0, o);
                    s1 += __shfl_xor_sync(0xFFFFFFFFu, s1, o);
                    q0 += __shfl_xor_sync(0xFFFFFFFFu, q0, o);
                    q1 += __shfl_xor_sync(0xFFFFFFFFu, q1, o);
                }
                if (lane < 4) {
                    sPartS[wid * 128 + c0] = s0;
                    sPartS[wid * 128 + c0 + 1] = s1;
                    sPartQ[wid * 128 + c0] = q0;
                    sPartQ[wid * 128 + c0 + 1] = q1;
                }
            }
        }
    }
    if (layer == 2) {
        __syncthreads();
        if (tid < 128) {
            float s = 0.f;
#pragma unroll
            for (int w = 0; w < 8; w++) s += sPartS[w * 128 + tid];
            atomicAdd(&g_stats[tid], s);
        } else {
            int c = tid - 128;
            float q = 0.f;
#pragma unroll
            for (int w = 0; w < 8; w++) q += sPartQ[w * 128 + c];
            atomicAdd(&g_stats[D + c], q);
        }
    }
}

// ===========================================================================
// Fused BN-normalize (zn out) + projection GEMM (HMMA split) + PReLU (p out)
// ===========================================================================
__global__ void __launch_bounds__(256)
proj_mma_kernel(const float* __restrict__ Wp,
                const float* __restrict__ bp,
                const float* __restrict__ gamma,
                const float* __restrict__ beta,
                const float* __restrict__ prelu_a,
                float* __restrict__ out) {
    extern __shared__ char smc[];
    __half* sAhi = (__half*)(smc + SM_AHI);
    __half* sAlo = (__half*)(smc + SM_ALO);
    __half* sWT  = (__half*)(smc + SM_WT);
    float* sScale = (float*)(smc + SM_SC);
    float* sShift = sScale + 128;

    int tid = threadIdx.x;
    int wid = tid >> 5, lane = tid & 31;
    int g = lane >> 2, ti = lane & 3;
    int row0 = blockIdx.x * 128;

    if (tid < D) {
        float mean = g_stats[tid] * (1.f / N_NODES);
        float var = g_stats[D + tid] * (1.f / N_NODES) - mean * mean;
        float rs = rsqrtf(var + BN_EPS);
        float sc = __ldg(&gamma[tid]) * rs;
        sScale[tid] = sc;
        sShift[tid] = __ldg(&beta[tid]) - mean * sc;
    }
    __syncthreads();

    float* zn_out = out;
    float* p_out = out + (size_t)N_NODES * D;

    for (int idx = tid; idx < D * D; idx += 256) {
        int r = idx >> 7, k = idx & 127;
        int gr = row0 + r;
        float zv = 0.f;
        if (gr < N_NODES) {
            zv = fmaf(g_z[(size_t)gr * D + k], sScale[k], sShift[k]);
            zn_out[(size_t)gr * D + k] = zv;
        }
        __half hi = __float2half_rn(zv);
        sAhi[r * SA + k] = hi;
        sAlo[r * SA + k] = __float2half_rn(zv - __half2float(hi));
    }
    fill_wt(Wp, sWT, tid, 0);
    __syncthreads();

    float C[16][4];
#pragma unroll
    for (int nt = 0; nt < 16; nt++)
#pragma unroll
        for (int j = 0; j < 4; j++) C[nt][j] = 0.f;

    gemm_pass<true>(sAhi, sAlo, sWT, C, wid, g, ti);
    __syncthreads();
    fill_wt(Wp, sWT, tid, 1);
    __syncthreads();
    gemm_pass<false>(sAhi, sAlo, sWT, C, wid, g, ti);

    {
        float a = __ldg(&prelu_a[0]);
        int lr = wid * 16 + g;
        int gr0 = row0 + lr, gr1 = gr0 + 8;
#pragma unroll
        for (int nt = 0; nt < 16; nt++) {
            int c0 = nt * 8 + ti * 2;
            float bv0 = __ldg(&bp[c0]), bv1 = __ldg(&bp[c0 + 1]);
            float v00 = C[nt][0] + bv0, v01 = C[nt][1] + bv1;
            float v10 = C[nt][2] + bv0, v11 = C[nt][3] + bv1;
            v00 = (v00 >= 0.f) ? v00 : a * v00;
            v01 = (v01 >= 0.f) ? v01 : a * v01;
            v10 = (v10 >= 0.f) ? v10 : a * v10;
            v11 = (v11 >= 0.f) ? v11 : a * v11;
            if (gr0 < N_NODES)
                *(float2*)&p_out[(size_t)gr0 * D + c0] = make_float2(v00, v01);
            if (gr1 < N_NODES)
                *(float2*)&p_out[(size_t)gr1 * D + c0] = make_float2(v10, v11);
        }
    }
}

// ---------------------------------------------------------------------------
extern "C" void kernel_launch(void* const* d_in, const int* in_sizes, int n_in,
                              void* d_out, int out_size) {
    const float* x       = (const float*)d_in[0];
    const float* ew      = (const float*)d_in[1];
    const float* W1s     = (const float*)d_in[2];
    const float* b1s     = (const float*)d_in[3];
    const float* W2s     = (const float*)d_in[4];
    const float* b2s     = (const float*)d_in[5];
    const float* eps     = (const float*)d_in[6];
    const float* gamma   = (const float*)d_in[7];
    const float* beta    = (const float*)d_in[8];
    const float* Wp      = (const float*)d_in[9];
    const float* bp      = (const float*)d_in[10];
    const float* prelu_a = (const float*)d_in[11];
    const int*   ei32    = (const int*)d_in[12];
    float* out = (float*)d_out;

    cudaFuncSetAttribute(mlp_mma_kernel, cudaFuncAttributeMaxDynamicSharedMemorySize, SM_MLP_TOTAL);
    cudaFuncSetAttribute(proj_mma_kernel, cudaFuncAttributeMaxDynamicSharedMemorySize, SM_PROJ_TOTAL);

    const int edgeBlocks = (N_EDGES + 255) / 256;           // 3125
    const int mmaBlocks  = (N_NODES + 127) / 128;           // 391
    const int aggBlocks  = (N_NODES * 32 + 255) / 256;      // 6250
    const int nodeBlocks = (N_NODES + 255) / 256;           // 196
    const int prepBlocks = (N_NODES * D / 4 + 255) / 256;   // 6250

    prep_kernel<<<prepBlocks, 256>>>(x, ei32);
    hist_kernel<<<edgeBlocks, 256>>>(ei32);
    scan_partial_kernel<<<N_CHUNKS, SCAN_CHUNK>>>();
    scan_add_kernel<<<nodeBlocks, 256>>>();
    scatter_kernel<<<edgeBlocks, 256>>>(ew, ei32);

    for (int l = 0; l < 3; l++) {
        agg_kernel<<<aggBlocks, 256>>>();
        mlp_mma_kernel<<<mmaBlocks, 256, SM_MLP_TOTAL>>>(x, W1s, b1s, W2s, b2s, eps, l);
    }
    proj_mma_kernel<<<mmaBlocks, 256, SM_PROJ_TOTAL>>>(Wp, bp, gamma, beta, prelu_a, out);
}

// round 15
// speedup vs baseline: 1.1039x; 1.1039x over previous
#include <cuda_runtime.h>
#include <cuda_fp16.h>
#include <cstdint>

#define N_NODES 50000
#define N_EDGES 800000
#define D 128
#define BN_EPS 1e-5f
#define SCAN_CHUNK 512
#define N_CHUNKS ((N_NODES + SCAN_CHUNK - 1) / SCAN_CHUNK)   // 98
#define SA 136                      // half stride for A/WT tiles (272B rows)
#define TILE_BYTES (128 * SA * 2)   // 34816
#define SM_AHI 0
#define SM_ALO TILE_BYTES           // 34816
#define SM_WT  (2 * TILE_BYTES)     // 69632
#define SM_MLP_TOTAL (3 * TILE_BYTES)         // 104448
#define SM_SC  SM_MLP_TOTAL
#define SM_PROJ_TOTAL (SM_MLP_TOTAL + 1024)

// Persistent scratch.
__device__ __align__(16) float g_z[N_NODES * D];
__device__ __align__(16) float g_agg[N_NODES * D];
__device__ float g_stats[2 * D];
__device__ int g_idx64;
__device__ int g_deg[N_NODES];
__device__ int g_cur[N_NODES];
__device__ int g_rowptr[N_NODES + 1];
__device__ int g_part[N_CHUNKS];
__device__ __align__(16) int2 g_epk[N_EDGES];   // packed (src, weight bits)

// ===========================================================================
// Zero counters/stats + probe edge_index dtype.
// ===========================================================================
__global__ void zero_counters_kernel(const int* __restrict__ ei32) {
    int i = blockIdx.x * blockDim.x + threadIdx.x;
    if (i < N_NODES) g_deg[i] = 0;
    if (i < 2 * D) g_stats[i] = 0.f;
    if (i == 0) {
        int all_zero = 1;
#pragma unroll
        for (int k = 0; k < 64; k++)
            if (__ldg(&ei32[2 * k + 1]) != 0) all_zero = 0;
        g_idx64 = all_zero;
    }
}

__device__ __forceinline__ int load_src(const int* ei32, int e) {
    int s = g_idx64 ? __ldg(&ei32[2 * e]) : __ldg(&ei32[e]);
    return min(max(s, 0), N_NODES - 1);
}
__device__ __forceinline__ int load_dst(const int* ei32, int e) {
    int d = g_idx64 ? __ldg(&ei32[2 * N_EDGES + 2 * e]) : __ldg(&ei32[N_EDGES + e]);
    return min(max(d, 0), N_NODES - 1);
}

__global__ void hist_kernel(const int* __restrict__ ei32) {
    int e = blockIdx.x * blockDim.x + threadIdx.x;
    if (e >= N_EDGES) return;
    atomicAdd(&g_deg[load_dst(ei32, e)], 1);
}

// Phase 1: per-chunk exclusive scan + chunk totals in g_part.
__global__ void scan_partial_kernel() {
    __shared__ int wsum[16];
    int tid = threadIdx.x, lane = tid & 31, wid = tid >> 5;
    int i = blockIdx.x * SCAN_CHUNK + tid;
    int v = (i < N_NODES) ? g_deg[i] : 0;
    int x = v;
#pragma unroll
    for (int o = 1; o < 32; o <<= 1) {
        int y = __shfl_up_sync(0xFFFFFFFFu, x, o);
        if (lane >= o) x += y;
    }
    if (lane == 31) wsum[wid] = x;
    __syncthreads();
    if (wid == 0 && lane < 16) {
        int w = wsum[lane];
#pragma unroll
        for (int o = 1; o < 16; o <<= 1) {
            int y = __shfl_up_sync(0x0000FFFFu, w, o);
            if (lane >= o) w += y;
        }
        wsum[lane] = w;
    }
    __syncthreads();
    int base = (wid > 0) ? wsum[wid - 1] : 0;
    if (i < N_NODES) g_rowptr[i] = base + x - v;
    if (tid == SCAN_CHUNK - 1) g_part[blockIdx.x] = base + x;
}

// Phase 2 (fused): thread 0 of each block sums its chunk prefix inline.
__global__ void scan_add_kernel() {
    __shared__ int s_off;
    int i = blockIdx.x * blockDim.x + threadIdx.x;
    int chunk = (blockIdx.x * 256) >> 9;
    if (threadIdx.x == 0) {
        int off = 0;
        for (int c = 0; c < chunk; c++) off += g_part[c];
        s_off = off;
    }
    __syncthreads();
    if (i < N_NODES) {
        int r = g_rowptr[i] + s_off;
        g_rowptr[i] = r;
        g_cur[i] = r;
    }
    if (i == N_NODES - 1) {
        int tot = s_off;
        for (int c = chunk; c < N_CHUNKS; c++) tot += g_part[c];
        g_rowptr[N_NODES] = tot;
    }
}

__global__ void scatter_kernel(const float* __restrict__ ew,
                               const int* __restrict__ ei32) {
    int e = blockIdx.x * blockDim.x + threadIdx.x;
    if (e >= N_EDGES) return;
    int src = load_src(ei32, e);
    int dst = load_dst(ei32, e);
    int pos = atomicAdd(&g_cur[dst], 1);
    g_epk[pos] = make_int2(src, __float_as_int(__ldg(&ew[e])));
}

// ===========================================================================
// CSR aggregation: fp32 float4 gather (round-13 pattern), packed CSR entries,
// 8-deep unroll for memory-level parallelism. One warp per node.
// ===========================================================================
__global__ void agg_kernel(const float* __restrict__ xin, int use_x) {
    int node = (blockIdx.x * blockDim.x + threadIdx.x) >> 5;
    if (node >= N_NODES) return;
    int lane = threadIdx.x & 31;
    const float* z = use_x ? xin : g_z;

    int beg = __ldg(&g_rowptr[node]);
    int end = __ldg(&g_rowptr[node + 1]);
    float4 acc = make_float4(0.f, 0.f, 0.f, 0.f);
    int e = beg;
#define AGG_ONE(EE)                                                      \
    do {                                                                 \
        int2 pk = __ldg(&g_epk[EE]);                                     \
        float w = __int_as_float(pk.y);                                  \
        float4 v = __ldg(&((const float4*)(z + (size_t)pk.x * D))[lane]);\
        acc.x = fmaf(v.x, w, acc.x); acc.y = fmaf(v.y, w, acc.y);        \
        acc.z = fmaf(v.z, w, acc.z); acc.w = fmaf(v.w, w, acc.w);        \
    } while (0)
    for (; e + 8 <= end; e += 8) {
        AGG_ONE(e);     AGG_ONE(e + 1); AGG_ONE(e + 2); AGG_ONE(e + 3);
        AGG_ONE(e + 4); AGG_ONE(e + 5); AGG_ONE(e + 6); AGG_ONE(e + 7);
    }
    for (; e < end; e++) AGG_ONE(e);
#undef AGG_ONE
    ((float4*)(g_agg + (size_t)node * D))[lane] = acc;
}

// ===========================================================================
// HMMA GEMM machinery (mma.sync m16n8k16, fp16 in / fp32 accum).
// Fragment mapping per PTX ISA; tiles [row][k] halves stride SA=136,
// conflict-free for all fragment loads.
// ===========================================================================
__device__ __forceinline__ void mma16816(float* c, uint32_t a0, uint32_t a1,
                                         uint32_t a2, uint32_t a3,
                                         uint32_t b0, uint32_t b1) {
    asm volatile(
        "mma.sync.aligned.m16n8k16.row.col.f32.f16.f16.f32 "
        "{%0,%1,%2,%3}, {%4,%5,%6,%7}, {%8,%9}, {%0,%1,%2,%3};"
        : "+f"(c[0]), "+f"(c[1]), "+f"(c[2]), "+f"(c[3])
        : "r"(a0), "r"(a1), "r"(a2), "r"(a3), "r"(b0), "r"(b1));
}

template <bool DUAL>
__device__ __forceinline__ void gemm_pass(const __half* sAhi, const __half* sAlo,
                                          const __half* sWT, float C[16][4],
                                          int wid, int g, int ti) {
    for (int ks = 0; ks < 8; ks++) {
        int k0 = ks * 16;
        int ra = (wid * 16 + g) * SA + ti * 2 + k0;
        uint32_t h0 = *(const uint32_t*)&sAhi[ra];
        uint32_t h1 = *(const uint32_t*)&sAhi[ra + 8 * SA];
        uint32_t h2 = *(const uint32_t*)&sAhi[ra + 8];
        uint32_t h3 = *(const uint32_t*)&sAhi[ra + 8 * SA + 8];
        uint32_t l0 = 0, l1 = 0, l2 = 0, l3 = 0;
        if (DUAL) {
            l0 = *(const uint32_t*)&sAlo[ra];
            l1 = *(const uint32_t*)&sAlo[ra + 8 * SA];
            l2 = *(const uint32_t*)&sAlo[ra + 8];
            l3 = *(const uint32_t*)&sAlo[ra + 8 * SA + 8];
        }
#pragma unroll
        for (int nt = 0; nt < 16; nt++) {
            int rb = (nt * 8 + g) * SA + ti * 2 + k0;
            uint32_t b0 = *(const uint32_t*)&sWT[rb];
            uint32_t b1 = *(const uint32_t*)&sWT[rb + 8];
            mma16816(C[nt], h0, h1, h2, h3, b0, b1);
            if (DUAL) mma16816(C[nt], l0, l1, l2, l3, b0, b1);
        }
    }
}

__device__ __forceinline__ void fill_wt(const float* __restrict__ W, __half* sWT,
                                        int tid, int part) {
    for (int idx = tid; idx < D * D; idx += 256) {
        int k = idx >> 7, n = idx & 127;
        float w = __ldg(&W[idx]);
        __half hi = __float2half_rn(w);
        sWT[n * SA + k] = part ? __float2half_rn(w - __half2float(hi)) : hi;
    }
}

__device__ __forceinline__ uint32_t pack_halves(float a, float b) {
    __half ha = __float2half_rn(a), hb = __float2half_rn(b);
    return (uint32_t)__half_as_ushort(ha) | ((uint32_t)__half_as_ushort(hb) << 16);
}

// ===========================================================================
// Fused GIN layer: two chained 128x128x128 GEMMs on HMMA, fp16 hi/lo split.
// Layer 2 fuses BN statistics.
// ===========================================================================
__global__ void __launch_bounds__(256)
mlp_mma_kernel(const float* __restrict__ xin,
               const float* __restrict__ W1s,
               const float* __restrict__ b1s,
               const float* __restrict__ W2s,
               const float* __restrict__ b2s,
               const float* __restrict__ epsp,
               int layer) {
    extern __shared__ char smc[];
    __half* sAhi = (__half*)(smc + SM_AHI);
    __half* sAlo = (__half*)(smc + SM_ALO);
    __half* sWT  = (__half*)(smc + SM_WT);

    int tid = threadIdx.x;
    int wid = tid >> 5, lane = tid & 31;
    int g = lane >> 2, ti = lane & 3;
    int row0 = blockIdx.x * 128;

    const float* zin = (layer == 0) ? xin : g_z;
    const float* W1 = W1s + layer * D * D;
    const float* W2 = W2s + layer * D * D;
    const float* b1 = b1s + layer * D;
    const float* b2 = b2s + layer * D;
    const float onePlusEps = 1.f + __ldg(&epsp[layer]);

    for (int idx = tid; idx < D * D; idx += 256) {
        int r = idx >> 7, k = idx & 127;
        int gr = row0 + r;
        float hv = 0.f;
        if (gr < N_NODES)
            hv = fmaf(onePlusEps, zin[(size_t)gr * D + k], g_agg[(size_t)gr * D + k]);
        __half hi = __float2half_rn(hv);
        sAhi[r * SA + k] = hi;
        sAlo[r * SA + k] = __float2half_rn(hv - __half2float(hi));
    }
    fill_wt(W1, sWT, tid, 0);
    __syncthreads();

    float C[16][4];
#pragma unroll
    for (int nt = 0; nt < 16; nt++)
#pragma unroll
        for (int j = 0; j < 4; j++) C[nt][j] = 0.f;

    gemm_pass<true>(sAhi, sAlo, sWT, C, wid, g, ti);
    __syncthreads();
    fill_wt(W1, sWT, tid, 1);
    __syncthreads();
    gemm_pass<false>(sAhi, sAlo, sWT, C, wid, g, ti);
    __syncthreads();

    // Epilogue 1: T = relu(C + b1) -> A tiles; zero C
    {
        int r0 = wid * 16 + g;
#pragma unroll
        for (int nt = 0; nt < 16; nt++) {
            int c0 = nt * 8 + ti * 2;
            float bv0 = __ldg(&b1[c0]), bv1 = __ldg(&b1[c0 + 1]);
            float t00 = fmaxf(C[nt][0] + bv0, 0.f);
            float t01 = fmaxf(C[nt][1] + bv1, 0.f);
            float t10 = fmaxf(C[nt][2] + bv0, 0.f);
            float t11 = fmaxf(C[nt][3] + bv1, 0.f);
            uint32_t p0 = pack_halves(t00, t01);
            uint32_t p1 = pack_halves(t10, t11);
            *(uint32_t*)&sAhi[r0 * SA + c0] = p0;
            *(uint32_t*)&sAhi[(r0 + 8) * SA + c0] = p1;
            __half h00 = __ushort_as_half((unsigned short)(p0 & 0xFFFF));
            __half h01 = __ushort_as_half((unsigned short)(p0 >> 16));
            __half h10 = __ushort_as_half((unsigned short)(p1 & 0xFFFF));
            __half h11 = __ushort_as_half((unsigned short)(p1 >> 16));
            *(uint32_t*)&sAlo[r0 * SA + c0] =
                pack_halves(t00 - __half2float(h00), t01 - __half2float(h01));
            *(uint32_t*)&sAlo[(r0 + 8) * SA + c0] =
                pack_halves(t10 - __half2float(h10), t11 - __half2float(h11));
#pragma unroll
            for (int j = 0; j < 4; j++) C[nt][j] = 0.f;
        }
    }
    fill_wt(W2, sWT, tid, 0);
    __syncthreads();

    gemm_pass<true>(sAhi, sAlo, sWT, C, wid, g, ti);
    __syncthreads();
    fill_wt(W2, sWT, tid, 1);
    __syncthreads();
    gemm_pass<false>(sAhi, sAlo, sWT, C, wid, g, ti);

    // Epilogue 2: z = relu(C + b2) -> g_z ; BN stats on layer 2
    float* sPartS = (float*)(smc + SM_ALO);
    float* sPartQ = sPartS + 1024;
    {
        int lr = wid * 16 + g;
        int gr0 = row0 + lr, gr1 = gr0 + 8;
#pragma unroll
        for (int nt = 0; nt < 16; nt++) {
            int c0 = nt * 8 + ti * 2;
            float bv0 = __ldg(&b2[c0]), bv1 = __ldg(&b2[c0 + 1]);
            float v00 = fmaxf(C[nt][0] + bv0, 0.f);
            float v01 = fmaxf(C[nt][1] + bv1, 0.f);
            float v10 = fmaxf(C[nt][2] + bv0, 0.f);
            float v11 = fmaxf(C[nt][3] + bv1, 0.f);
            if (gr0 < N_NODES) {
                *(float2*)&g_z[(size_t)gr0 * D + c0] = make_float2(v00, v01);
            } else { v00 = v01 = 0.f; }
            if (gr1 < N_NODES) {
                *(float2*)&g_z[(size_t)gr1 * D + c0] = make_float2(v10, v11);
            } else { v10 = v11 = 0.f; }
            if (layer == 2) {
                float s0 = v00 + v10, s1 = v01 + v11;
                float q0 = v00 * v00 + v10 * v10, q1 = v01 * v01 + v11 * v11;
#pragma unroll
                for (int o = 4; o < 32; o <<= 1) {
                    s0 += __shfl_xor_sync(0xFFFFFFFFu, s0, o);
                    s1 += __shfl_xor_sync(0xFFFFFFFFu, s1, o);
                    q0 += __shfl_xor_sync(0xFFFFFFFFu, q0, o);
                    q1 += __shfl_xor_sync(0xFFFFFFFFu, q1, o);
                }
                if (lane < 4) {
                    sPartS[wid * 128 + c0] = s0;
                    sPartS[wid * 128 + c0 + 1] = s1;
                    sPartQ[wid * 128 + c0] = q0;
                    sPartQ[wid * 128 + c0 + 1] = q1;
                }
            }
        }
    }
    if (layer == 2) {
        __syncthreads();
        if (tid < 128) {
            float s = 0.f;
#pragma unroll
            for (int w = 0; w < 8; w++) s += sPartS[w * 128 + tid];
            atomicAdd(&g_stats[tid], s);
        } else {
            int c = tid - 128;
            float q = 0.f;
#pragma unroll
            for (int w = 0; w < 8; w++) q += sPartQ[w * 128 + c];
            atomicAdd(&g_stats[D + c], q);
        }
    }
}

// ===========================================================================
// Fused BN-normalize (zn out) + projection GEMM (HMMA split) + PReLU (p out)
// ===========================================================================
__global__ void __launch_bounds__(256)
proj_mma_kernel(const float* __restrict__ Wp,
                const float* __restrict__ bp,
                const float* __restrict__ gamma,
                const float* __restrict__ beta,
                const float* __restrict__ prelu_a,
                float* __restrict__ out) {
    extern __shared__ char smc[];
    __half* sAhi = (__half*)(smc + SM_AHI);
    __half* sAlo = (__half*)(smc + SM_ALO);
    __half* sWT  = (__half*)(smc + SM_WT);
    float* sScale = (float*)(smc + SM_SC);
    float* sShift = sScale + 128;

    int tid = threadIdx.x;
    int wid = tid >> 5, lane = tid & 31;
    int g = lane >> 2, ti = lane & 3;
    int row0 = blockIdx.x * 128;

    if (tid < D) {
        float mean = g_stats[tid] * (1.f / N_NODES);
        float var = g_stats[D + tid] * (1.f / N_NODES) - mean * mean;
        float rs = rsqrtf(var + BN_EPS);
        float sc = __ldg(&gamma[tid]) * rs;
        sScale[tid] = sc;
        sShift[tid] = __ldg(&beta[tid]) - mean * sc;
    }
    __syncthreads();

    float* zn_out = out;
    float* p_out = out + (size_t)N_NODES * D;

    for (int idx = tid; idx < D * D; idx += 256) {
        int r = idx >> 7, k = idx & 127;
        int gr = row0 + r;
        float zv = 0.f;
        if (gr < N_NODES) {
            zv = fmaf(g_z[(size_t)gr * D + k], sScale[k], sShift[k]);
            zn_out[(size_t)gr * D + k] = zv;
        }
        __half hi = __float2half_rn(zv);
        sAhi[r * SA + k] = hi;
        sAlo[r * SA + k] = __float2half_rn(zv - __half2float(hi));
    }
    fill_wt(Wp, sWT, tid, 0);
    __syncthreads();

    float C[16][4];
#pragma unroll
    for (int nt = 0; nt < 16; nt++)
#pragma unroll
        for (int j = 0; j < 4; j++) C[nt][j] = 0.f;

    gemm_pass<true>(sAhi, sAlo, sWT, C, wid, g, ti);
    __syncthreads();
    fill_wt(Wp, sWT, tid, 1);
    __syncthreads();
    gemm_pass<false>(sAhi, sAlo, sWT, C, wid, g, ti);

    {
        float a = __ldg(&prelu_a[0]);
        int lr = wid * 16 + g;
        int gr0 = row0 + lr, gr1 = gr0 + 8;
#pragma unroll
        for (int nt = 0; nt < 16; nt++) {
            int c0 = nt * 8 + ti * 2;
            float bv0 = __ldg(&bp[c0]), bv1 = __ldg(&bp[c0 + 1]);
            float v00 = C[nt][0] + bv0, v01 = C[nt][1] + bv1;
            float v10 = C[nt][2] + bv0, v11 = C[nt][3] + bv1;
            v00 = (v00 >= 0.f) ? v00 : a * v00;
            v01 = (v01 >= 0.f) ? v01 : a * v01;
            v10 = (v10 >= 0.f) ? v10 : a * v10;
            v11 = (v11 >= 0.f) ? v11 : a * v11;
            if (gr0 < N_NODES)
                *(float2*)&p_out[(size_t)gr0 * D + c0] = make_float2(v00, v01);
            if (gr1 < N_NODES)
                *(float2*)&p_out[(size_t)gr1 * D + c0] = make_float2(v10, v11);
        }
    }
}

// ---------------------------------------------------------------------------
extern "C" void kernel_launch(void* const* d_in, const int* in_sizes, int n_in,
                              void* d_out, int out_size) {
    const float* x       = (const float*)d_in[0];
    const float* ew      = (const float*)d_in[1];
    const float* W1s     = (const float*)d_in[2];
    const float* b1s     = (const float*)d_in[3];
    const float* W2s     = (const float*)d_in[4];
    const float* b2s     = (const float*)d_in[5];
    const float* eps     = (const float*)d_in[6];
    const float* gamma   = (const float*)d_in[7];
    const float* beta    = (const float*)d_in[8];
    const float* Wp      = (const float*)d_in[9];
    const float* bp      = (const float*)d_in[10];
    const float* prelu_a = (const float*)d_in[11];
    const int*   ei32    = (const int*)d_in[12];
    float* out = (float*)d_out;

    cudaFuncSetAttribute(mlp_mma_kernel, cudaFuncAttributeMaxDynamicSharedMemorySize, SM_MLP_TOTAL);
    cudaFuncSetAttribute(proj_mma_kernel, cudaFuncAttributeMaxDynamicSharedMemorySize, SM_PROJ_TOTAL);

    const int edgeBlocks = (N_EDGES + 255) / 256;           // 3125
    const int mmaBlocks  = (N_NODES + 127) / 128;           // 391
    const int aggBlocks  = (N_NODES * 32 + 255) / 256;      // 6250
    const int nodeBlocks = (N_NODES + 255) / 256;           // 196

    zero_counters_kernel<<<nodeBlocks, 256>>>(ei32);
    hist_kernel<<<edgeBlocks, 256>>>(ei32);
    scan_partial_kernel<<<N_CHUNKS, SCAN_CHUNK>>>();
    scan_add_kernel<<<nodeBlocks, 256>>>();
    scatter_kernel<<<edgeBlocks, 256>>>(ew, ei32);

    for (int l = 0; l < 3; l++) {
        agg_kernel<<<aggBlocks, 256>>>(x, l == 0 ? 1 : 0);
        mlp_mma_kernel<<<mmaBlocks, 256, SM_MLP_TOTAL>>>(x, W1s, b1s, W2s, b2s, eps, l);
    }
    proj_mma_kernel<<<mmaBlocks, 256, SM_PROJ_TOTAL>>>(Wp, bp, gamma, beta, prelu_a, out);
}